// round 11
// baseline (speedup 1.0000x reference)
#include <cuda_runtime.h>
#include <cuda_bf16.h>

// PSAvgPooling: B=8, H=W=64, C=1152 (= 9 bins * 128), N=512 boxes/image,
// 3x3 bins x 3x3 crop samples, bilinear gather, weighted bin-average.
//
// R10 = R8 with Phase-A hardening (merge built in clamped register-local
// arrays; arithmetic identical in all reachable cases). R9/R10 bench errors
// were container infra; kernel never ran.
//
// R8 idea: separable corner deduplication.
// Measured law (R2d/R5/R7): time == 2.07 cyc per 128B line-access wavefront,
// independent of LDG width. So reduce wavefronts: within each bin the 9 crop
// samples' bilinear sum factorizes into (row weights) x (col weights); gather
// each distinct cell ONCE with weight wts[bin]*rw[i]*cw[j].
//   cells/bin = nR*nC <= 36, typically ~25 (down to 9 for small boxes).

namespace {

constexpr int Hh    = 64;
constexpr int Ww    = 64;
constexpr int Cc    = 1152;   // total channels
constexpr int Csz   = 128;    // channels per bin (Cc / 9)
constexpr int NSAMP_MAX = 36; // max cells per bin
constexpr int NWARP = 4;      // warps per box

__global__ __launch_bounds__(NWARP * 32, 8) void ps_pool_kernel(
    const float* __restrict__ img,    // [B, H, W, C]
    const float* __restrict__ boxes,  // [B*N, 4]  (y1,x1,y2,x2 normalized)
    const float* __restrict__ wts,    // [9]
    float* __restrict__ out,          // [B*N, 128]
    int nPerImage)
{
    __shared__ float s_axw[9][2][6];      // merged axis weights [bin][0=y,1=x][slot]
    __shared__ int   s_axr[9][2][6];      // merged axis indices (row / col)
    __shared__ int   s_axn[9][2];         // axis counts
    __shared__ int   s_coff[9][NSAMP_MAX];   // cell BYTE offsets (incl. bin*128ch)
    __shared__ float s_cw[9][NSAMP_MAX];     // cell weights
    __shared__ int   s_cn[9];                // cells per bin
    __shared__ float4 s_red[NWARP][32];      // per-warp partial accumulators

    const int box_id = blockIdx.x;
    const int b      = box_id / nPerImage;
    const float* __restrict__ image = img + (size_t)b * (Hh * Ww * Cc);
    const float* bx = boxes + (size_t)box_id * 4;
    const int tid  = threadIdx.x;
    const int lane = tid & 31;
    const int warp = tid >> 5;

    // ---- Phase A: 18 threads build merged per-axis lists (bin, axis) ----
    // Built in register-local arrays with clamped indices (no OOB possible),
    // then stored to smem.
    if (tid < 18) {
        const int bin  = tid >> 1;
        const int axis = tid & 1;                  // 0 = y, 1 = x
        const int bidx = axis ? (bin % 3) : (bin / 3);
        const float lo0  = axis ? bx[1] : bx[0];
        const float hi0  = axis ? bx[3] : bx[2];
        const float step = (hi0 - lo0) * (1.0f / 3.0f);
        const float lim  = axis ? (float)(Ww - 1) : (float)(Hh - 1);
        const int   limi = axis ? (Ww - 1) : (Hh - 1);

        int   lr[6];
        float lw[6];
        int n = 0;
        int M = -100;
        #pragma unroll
        for (int p = 0; p < 3; p++) {
            const float c = (lo0 + ((float)bidx + (float)p * 0.5f) * step) * lim;
            const float f = floorf(c);
            const float w = c - f;
            const int   fi = (int)f;
            const int   loI = min(max(fi,     0), limi);
            const int   hiI = min(max(fi + 1, 0), limi);
            const float m   = (c >= 0.0f && c <= lim) ? 1.0f : 0.0f;
            const float wlo = (1.0f - w) * m;
            const float whi = w * m;

            const int i1 = max(n - 1, 0);   // clamped (unreachable-case safety)
            const int i2 = max(n - 2, 0);

            if (loI > M) {
                lr[n] = loI; lw[n] = wlo; n++;
                if (hiI > loI) { lr[n] = hiI; lw[n] = whi; n++; }
                else           { lw[n - 1] += whi; }
            } else if (loI == M) {
                lw[i1] += wlo;
                if (hiI > M) { lr[n] = hiI; lw[n] = whi; n++; }
                else         { lw[n - 1] += whi; }  // hiI == M (c == lim)
            } else {            // loI == M-1, hiI == M (tail is contiguous)
                lw[i2] += wlo;
                lw[i1] += whi;
            }
            M = max(M, hiI);
        }
        #pragma unroll
        for (int k = 0; k < 6; k++) {
            if (k < n) { s_axr[bin][axis][k] = lr[k]; s_axw[bin][axis][k] = lw[k]; }
        }
        s_axn[bin][axis] = n;
    }
    __syncthreads();

    // ---- Phase B: all 128 threads emit rank-1 cell lists (no atomics) ----
    for (int idx = tid; idx < 9 * NSAMP_MAX; idx += NWARP * 32) {
        const int bin = idx / NSAMP_MAX;
        const int k   = idx % NSAMP_MAX;
        const int nR = s_axn[bin][0];
        const int nC = s_axn[bin][1];
        if (k == 0) s_cn[bin] = nR * nC;
        if (k < nR * nC) {
            const int i = k / nC;
            const int j = k % nC;
            const int row = s_axr[bin][0][i];
            const int col = s_axr[bin][1][j];
            s_coff[bin][k] = ((row * Ww + col) * Cc + bin * Csz) * 4;  // byte offset
            s_cw[bin][k]   = wts[bin] * s_axw[bin][0][i] * s_axw[bin][1][j];
        }
    }
    __syncthreads();

    // ---- Phase C: warps gather distinct cells (LDG.128, lane*16 within 512B slab) ----
    const char* __restrict__ base = (const char*)image + lane * 16;
    float4 acc = make_float4(0.f, 0.f, 0.f, 0.f);

    #pragma unroll
    for (int bin = 0; bin < 9; bin++) {
        const int n = s_cn[bin];
        for (int k = warp; k < n; k += NWARP) {
            const int   off = s_coff[bin][k];
            const float w   = s_cw[bin][k];
            const float4 v  = __ldg((const float4*)(base + off));
            acc.x += w * v.x;
            acc.y += w * v.y;
            acc.z += w * v.z;
            acc.w += w * v.w;
        }
    }

    s_red[warp][lane] = acc;
    __syncthreads();

    // ---- First warp reduces the 4 partials and writes out ----
    if (warp == 0) {
        float4 a0 = s_red[0][lane];
        float4 a1 = s_red[1][lane];
        float4 a2 = s_red[2][lane];
        float4 a3 = s_red[3][lane];
        const float inv = 1.0f / 81.0f;  // mean over 9 samples, then /9 bins
        float4 o;
        o.x = (a0.x + a1.x + a2.x + a3.x) * inv;
        o.y = (a0.y + a1.y + a2.y + a3.y) * inv;
        o.z = (a0.z + a1.z + a2.z + a3.z) * inv;
        o.w = (a0.w + a1.w + a2.w + a3.w) * inv;
        reinterpret_cast<float4*>(out)[(size_t)box_id * (Csz / 4) + lane] = o;
    }
}

} // namespace

extern "C" void kernel_launch(void* const* d_in, const int* in_sizes, int n_in,
                              void* d_out, int out_size) {
    const float* img   = (const float*)d_in[0];  // [B,64,64,1152] fp32
    const float* boxes = (const float*)d_in[1];  // [B,N,4] fp32
    const float* wts   = (const float*)d_in[2];  // [9] fp32
    float* out = (float*)d_out;                  // [B*N, 128] fp32

    const int B          = in_sizes[0] / (Hh * Ww * Cc);
    const int totalBoxes = in_sizes[1] / 4;
    const int nPerImage  = totalBoxes / B;

    ps_pool_kernel<<<totalBoxes, NWARP * 32>>>(img, boxes, wts, out, nPerImage);
}

// round 12
// speedup vs baseline: 1.1365x; 1.1365x over previous
#include <cuda_runtime.h>
#include <cuda_bf16.h>

// PSAvgPooling: B=8, H=W=64, C=1152 (= 9 bins * 128), N=512 boxes/image,
// 3x3 bins x 3x3 crop samples, bilinear gather, weighted bin-average.
//
// R11: separable dedup (R8) + STATIC gather loop (R2d shape).
// R10 taught us the binder is exposed latency / MLP, not wavefront throughput:
// data-dependent loop bounds killed load batching and regressed 41->52us.
// Here the deduped cells (9 bins x nR*nC, typ ~225 vs 324) are flattened into
// one compact list padded to a multiple of 16 with weight-0 dummy cells, so
// phase C is the proven R2d loop (int4 off + float4 w + 4x LDG.128), just
// with ~30% fewer iterations.

namespace {

constexpr int Hh    = 64;
constexpr int Ww    = 64;
constexpr int Cc    = 1152;   // total channels
constexpr int Csz   = 128;    // channels per bin (Cc / 9)
constexpr int NWARP = 4;      // warps per box
constexpr int MAXC  = 336;    // 9*36 = 324 cells max, padded up to multiple of 16

__global__ __launch_bounds__(NWARP * 32, 8) void ps_pool_kernel(
    const float* __restrict__ img,    // [B, H, W, C]
    const float* __restrict__ boxes,  // [B*N, 4]  (y1,x1,y2,x2 normalized)
    const float* __restrict__ wts,    // [9]
    float* __restrict__ out,          // [B*N, 128]
    int nPerImage)
{
    __shared__ float s_axw[9][2][6];       // merged axis weights [bin][0=y,1=x][slot]
    __shared__ int   s_axr[9][2][6];       // merged axis indices (row / col)
    __shared__ int   s_axn[9][2];          // axis counts
    __shared__ int   s_start[10];          // flat-list start per bin; [9] = total
    __shared__ __align__(16) int   s_coff[MAXC];  // flat cell BYTE offsets
    __shared__ __align__(16) float s_cw[MAXC];    // flat cell weights (0 = dummy pad)
    __shared__ float4 s_red[NWARP][32];    // per-warp partial accumulators

    const int box_id = blockIdx.x;
    const int b      = box_id / nPerImage;
    const float* __restrict__ image = img + (size_t)b * (Hh * Ww * Cc);
    const float* bx = boxes + (size_t)box_id * 4;
    const int tid  = threadIdx.x;
    const int lane = tid & 31;
    const int warp = tid >> 5;

    // ---- Phase A: 18 threads build merged per-axis lists (bin, axis) ----
    if (tid < 18) {
        const int bin  = tid >> 1;
        const int axis = tid & 1;                  // 0 = y, 1 = x
        const int bidx = axis ? (bin % 3) : (bin / 3);
        const float lo0  = axis ? bx[1] : bx[0];
        const float hi0  = axis ? bx[3] : bx[2];
        const float step = (hi0 - lo0) * (1.0f / 3.0f);
        const float lim  = axis ? (float)(Ww - 1) : (float)(Hh - 1);
        const int   limi = axis ? (Ww - 1) : (Hh - 1);

        int   lr[6];
        float lw[6];
        int n = 0;
        int M = -100;
        #pragma unroll
        for (int p = 0; p < 3; p++) {
            const float c = (lo0 + ((float)bidx + (float)p * 0.5f) * step) * lim;
            const float f = floorf(c);
            const float w = c - f;
            const int   fi = (int)f;
            const int   loI = min(max(fi,     0), limi);
            const int   hiI = min(max(fi + 1, 0), limi);
            const float m   = (c >= 0.0f && c <= lim) ? 1.0f : 0.0f;
            const float wlo = (1.0f - w) * m;
            const float whi = w * m;

            const int i1 = max(n - 1, 0);   // clamped (unreachable-case safety)
            const int i2 = max(n - 2, 0);

            if (loI > M) {
                lr[n] = loI; lw[n] = wlo; n++;
                if (hiI > loI) { lr[n] = hiI; lw[n] = whi; n++; }
                else           { lw[n - 1] += whi; }
            } else if (loI == M) {
                lw[i1] += wlo;
                if (hiI > M) { lr[n] = hiI; lw[n] = whi; n++; }
                else         { lw[n - 1] += whi; }  // hiI == M (c == lim)
            } else {            // loI == M-1, hiI == M (tail is contiguous)
                lw[i2] += wlo;
                lw[i1] += whi;
            }
            M = max(M, hiI);
        }
        #pragma unroll
        for (int k = 0; k < 6; k++) {
            if (k < n) { s_axr[bin][axis][k] = lr[k]; s_axw[bin][axis][k] = lw[k]; }
        }
        s_axn[bin][axis] = n;
    }
    __syncthreads();

    // ---- Phase A2: one thread computes flat-list starts ----
    if (tid == 0) {
        int acc = 0;
        #pragma unroll
        for (int bin = 0; bin < 9; bin++) {
            s_start[bin] = acc;
            acc += s_axn[bin][0] * s_axn[bin][1];
        }
        s_start[9] = acc;
    }
    __syncthreads();

    // ---- Phase B: emit flat cell list + zero-pad to multiple of 16 ----
    #pragma unroll
    for (int bin = 0; bin < 9; bin++) {
        const int nR = s_axn[bin][0];
        const int nC = s_axn[bin][1];
        const int n  = nR * nC;
        const int st = s_start[bin];
        const float wb = wts[bin];
        const int cb = bin * Csz;
        for (int k = tid; k < n; k += NWARP * 32) {
            const int i = k / nC;
            const int j = k % nC;
            const int row = s_axr[bin][0][i];
            const int col = s_axr[bin][1][j];
            s_coff[st + k] = ((row * Ww + col) * Cc + cb) * 4;  // byte offset
            s_cw[st + k]   = wb * s_axw[bin][0][i] * s_axw[bin][1][j];
        }
    }
    {
        const int total    = s_start[9];
        const int padTotal = (total + 15) & ~15;
        for (int k = total + tid; k < padTotal; k += NWARP * 32) {
            s_coff[k] = 0;       // safe load target
            s_cw[k]   = 0.0f;    // contributes nothing
        }
    }
    __syncthreads();

    // ---- Phase C: static-shape gather (R2d-proven): 4x LDG.128 per iter ----
    const char* __restrict__ base = (const char*)image + lane * 16;
    const int padTotal = (s_start[9] + 15) & ~15;
    float4 acc = make_float4(0.f, 0.f, 0.f, 0.f);

    #pragma unroll 2
    for (int cb4 = warp * 4; cb4 < padTotal; cb4 += NWARP * 4) {
        const int4   off = *reinterpret_cast<const int4*>(&s_coff[cb4]);
        const float4 w   = *reinterpret_cast<const float4*>(&s_cw[cb4]);
        const float4 v0 = __ldg((const float4*)(base + off.x));
        const float4 v1 = __ldg((const float4*)(base + off.y));
        const float4 v2 = __ldg((const float4*)(base + off.z));
        const float4 v3 = __ldg((const float4*)(base + off.w));
        acc.x += w.x * v0.x + w.y * v1.x + w.z * v2.x + w.w * v3.x;
        acc.y += w.x * v0.y + w.y * v1.y + w.z * v2.y + w.w * v3.y;
        acc.z += w.x * v0.z + w.y * v1.z + w.z * v2.z + w.w * v3.z;
        acc.w += w.x * v0.w + w.y * v1.w + w.z * v2.w + w.w * v3.w;
    }

    s_red[warp][lane] = acc;
    __syncthreads();

    // ---- First warp reduces the 4 partials and writes out ----
    if (warp == 0) {
        float4 a0 = s_red[0][lane];
        float4 a1 = s_red[1][lane];
        float4 a2 = s_red[2][lane];
        float4 a3 = s_red[3][lane];
        const float inv = 1.0f / 81.0f;  // mean over 9 samples, then /9 bins
        float4 o;
        o.x = (a0.x + a1.x + a2.x + a3.x) * inv;
        o.y = (a0.y + a1.y + a2.y + a3.y) * inv;
        o.z = (a0.z + a1.z + a2.z + a3.z) * inv;
        o.w = (a0.w + a1.w + a2.w + a3.w) * inv;
        reinterpret_cast<float4*>(out)[(size_t)box_id * (Csz / 4) + lane] = o;
    }
}

} // namespace

extern "C" void kernel_launch(void* const* d_in, const int* in_sizes, int n_in,
                              void* d_out, int out_size) {
    const float* img   = (const float*)d_in[0];  // [B,64,64,1152] fp32
    const float* boxes = (const float*)d_in[1];  // [B,N,4] fp32
    const float* wts   = (const float*)d_in[2];  // [9] fp32
    float* out = (float*)d_out;                  // [B*N, 128] fp32

    const int B          = in_sizes[0] / (Hh * Ww * Cc);
    const int totalBoxes = in_sizes[1] / 4;
    const int nPerImage  = totalBoxes / B;

    ps_pool_kernel<<<totalBoxes, NWARP * 32>>>(img, boxes, wts, out, nPerImage);
}